// round 1
// baseline (speedup 1.0000x reference)
#include <cuda_runtime.h>
#include <math.h>

#define Bsz   128
#define TIN   64
#define TOUT  90
#define HIDD  1024
#define H3    3072
#define EMBD  300
#define POSEN 514

// ---------------- scratch (device globals; no allocation allowed) ----------
__device__ float g_gi_enc[2][TIN * Bsz * H3];     // per-dir precomputed x@Wih^T + bih
__device__ float g_gi_dec[TOUT * Bsz * H3];       // decoder input gates
__device__ float g_h_enc[2][2][Bsz * HIDD];       // [dir][pingpong]
__device__ float g_dec_h0[Bsz * HIDD];
__device__ float g_hs[TOUT * Bsz * HIDD];         // decoder hidden states

// ---------------- bulk GEMM: C[m,n] = gather_row(m) . W[n,:] + bias[n] -----
// MODE 0: encoder input  (A row = enc_emb[in_text[b,t]], K=300, out g_gi_enc[z])
// MODE 1: decoder input  (A row = dec_emb[poses[b, max(t-1,0)]], K=1024, out g_gi_dec)
// MODE 2: final FC       (A row = g_hs[m], K=1024, N=514, out Cout)
template <int MODE>
__global__ void __launch_bounds__(256) gemm_big(
    const float* __restrict__ Aemb, const int* __restrict__ idx,
    const float* __restrict__ W0, const float* __restrict__ b0,
    const float* __restrict__ W1, const float* __restrict__ b1,
    float* __restrict__ Cout, int N, int K)
{
    const float* W    = W0;
    const float* bias = b0;
    if (MODE == 0 && blockIdx.z == 1) { W = W1; bias = b1; }

    __shared__ float As[32][68];   // As[k][m], pad keeps float4 alignment
    __shared__ float Bs[32][68];   // Bs[k][n]

    const int tid  = threadIdx.x;
    const int tx   = tid & 15;
    const int ty   = tid >> 4;
    const int lrow = tid >> 5;     // 0..7
    const int lk   = tid & 31;     // 0..31

    // precompute gathered A row pointers (8 rows per thread-group)
    const float* aptr[8];
#pragma unroll
    for (int i = 0; i < 8; i++) {
        int m = blockIdx.y * 64 + i * 8 + lrow;
        if (MODE == 0) {
            int t = m >> 7, b = m & 127;
            int tok = idx[b * TIN + t];
            aptr[i] = Aemb + (size_t)tok * EMBD;
        } else if (MODE == 1) {
            int t = m >> 7, b = m & 127;
            int ti = (t == 0) ? 0 : (t - 1);
            int pi = idx[b * TOUT + ti];
            aptr[i] = Aemb + (size_t)pi * HIDD;
        } else {
            aptr[i] = g_hs + (size_t)m * HIDD;
        }
    }

    float acc[4][4] = {};

    for (int kt = 0; kt < K; kt += 32) {
#pragma unroll
        for (int i = 0; i < 8; i++) {
            int kg = kt + lk;
            As[lk][i * 8 + lrow] = (kg < K) ? aptr[i][kg] : 0.f;
        }
#pragma unroll
        for (int i = 0; i < 8; i++) {
            int n  = blockIdx.x * 64 + i * 8 + lrow;
            int kg = kt + lk;
            float v = 0.f;
            if (n < N && kg < K) v = W[(size_t)n * K + kg];
            Bs[lk][i * 8 + lrow] = v;
        }
        __syncthreads();
#pragma unroll
        for (int kk = 0; kk < 32; kk++) {
            float4 a4 = *(const float4*)&As[kk][ty * 4];
            float4 b4 = *(const float4*)&Bs[kk][tx * 4];
            float av[4] = {a4.x, a4.y, a4.z, a4.w};
            float bv[4] = {b4.x, b4.y, b4.z, b4.w};
#pragma unroll
            for (int r = 0; r < 4; r++)
#pragma unroll
                for (int c = 0; c < 4; c++)
                    acc[r][c] += av[r] * bv[c];
        }
        __syncthreads();
    }

#pragma unroll
    for (int r = 0; r < 4; r++) {
        int m = blockIdx.y * 64 + ty * 4 + r;
#pragma unroll
        for (int c = 0; c < 4; c++) {
            int n = blockIdx.x * 64 + tx * 4 + c;
            if (n < N) {
                float v = acc[r][c] + bias[n];
                if (MODE == 0)      g_gi_enc[blockIdx.z][(size_t)m * H3 + n] = v;
                else if (MODE == 1) g_gi_dec[(size_t)m * H3 + n] = v;
                else                Cout[(size_t)m * POSEN + n] = v;
            }
        }
    }
}

// ---------------- fused recurrent step ------------------------------------
// One block computes a 32(batch) x 32(hidden) tile of h', accumulating the
// three gate chunks (r,z,n) of gh = h@Whh^T over K=1024, then applies GRU
// gate math with the precomputed gi in the epilogue.
// mode 0: encoder (blockIdx.z = direction), mode 1: decoder.
__global__ void __launch_bounds__(128) gru_step(
    int mode, int t,
    const float* __restrict__ W0, const float* __restrict__ b0,
    const float* __restrict__ W1, const float* __restrict__ b1)
{
    const float* Whh = (blockIdx.z == 1) ? W1 : W0;
    const float* bhh = (blockIdx.z == 1) ? b1 : b0;

    const float* h_in;
    float*       h_out;
    const float* gi;
    if (mode == 0) {
        int d = blockIdx.z;
        h_in  = g_h_enc[d][t & 1];
        h_out = g_h_enc[d][(t & 1) ^ 1];
        gi    = g_gi_enc[d] + (size_t)t * Bsz * H3;
    } else {
        h_in  = (t == 0) ? g_dec_h0 : (g_hs + (size_t)(t - 1) * Bsz * HIDD);
        h_out = g_hs + (size_t)t * Bsz * HIDD;
        gi    = g_gi_dec + (size_t)t * Bsz * H3;
    }

    __shared__ float As[32][36];       // As[k][m]
    __shared__ float Ws[3][32][34];    // Ws[chunk][k][n]

    const int tid  = threadIdx.x;
    const int tx   = tid & 15;         // 0..15 -> 2 cols each
    const int ty   = tid >> 4;         // 0..7  -> 4 rows each
    const int lrow = tid >> 5;         // 0..3
    const int lk   = tid & 31;
    const int m0   = blockIdx.y * 32;
    const int n0   = blockIdx.x * 32;

    float acc[3][4][2] = {};

    for (int kt = 0; kt < HIDD; kt += 32) {
#pragma unroll
        for (int i = 0; i < 8; i++) {
            int r = i * 4 + lrow;
            As[lk][r] = h_in[(size_t)(m0 + r) * HIDD + kt + lk];
        }
#pragma unroll
        for (int c = 0; c < 3; c++) {
#pragma unroll
            for (int i = 0; i < 8; i++) {
                int r  = i * 4 + lrow;
                int ng = c * HIDD + n0 + r;
                Ws[c][lk][r] = Whh[(size_t)ng * HIDD + kt + lk];
            }
        }
        __syncthreads();
#pragma unroll
        for (int kk = 0; kk < 32; kk++) {
            float4 a4 = *(const float4*)&As[kk][ty * 4];
            float2 w0 = *(const float2*)&Ws[0][kk][tx * 2];
            float2 w1 = *(const float2*)&Ws[1][kk][tx * 2];
            float2 w2 = *(const float2*)&Ws[2][kk][tx * 2];
            float av[4] = {a4.x, a4.y, a4.z, a4.w};
#pragma unroll
            for (int r = 0; r < 4; r++) {
                acc[0][r][0] += av[r] * w0.x;  acc[0][r][1] += av[r] * w0.y;
                acc[1][r][0] += av[r] * w1.x;  acc[1][r][1] += av[r] * w1.y;
                acc[2][r][0] += av[r] * w2.x;  acc[2][r][1] += av[r] * w2.y;
            }
        }
        __syncthreads();
    }

#pragma unroll
    for (int r = 0; r < 4; r++) {
        int m = m0 + ty * 4 + r;
        const float* gim = gi + (size_t)m * H3;
#pragma unroll
        for (int j = 0; j < 2; j++) {
            int jg = n0 + tx * 2 + j;
            float ghr = acc[0][r][j] + bhh[jg];
            float ghz = acc[1][r][j] + bhh[HIDD + jg];
            float ghn = acc[2][r][j] + bhh[2 * HIDD + jg];
            float rr = 1.f / (1.f + expf(-(gim[jg] + ghr)));
            float zz = 1.f / (1.f + expf(-(gim[HIDD + jg] + ghz)));
            float nn = tanhf(gim[2 * HIDD + jg] + rr * ghn);
            h_out[(size_t)m * HIDD + jg] =
                (1.f - zz) * nn + zz * h_in[(size_t)m * HIDD + jg];
        }
    }
}

// ---------------- small helpers -------------------------------------------
__global__ void zero_h()
{
    int i = blockIdx.x * blockDim.x + threadIdx.x;
    if (i < Bsz * HIDD) {
        g_h_enc[0][0][i] = 0.f;
        g_h_enc[1][0][i] = 0.f;
    }
}

__global__ void combine_h0()
{
    int i = blockIdx.x * blockDim.x + threadIdx.x;
    if (i < Bsz * HIDD)
        g_dec_h0[i] = g_h_enc[0][0][i] + g_h_enc[1][0][i];
}

// ---------------- launch ----------------------------------------------------
extern "C" void kernel_launch(void* const* d_in, const int* in_sizes, int n_in,
                              void* d_out, int out_size)
{
    const float* enc_emb   = (const float*)d_in[0];
    const float* enc_Wih_f = (const float*)d_in[1];
    const float* enc_Whh_f = (const float*)d_in[2];
    const float* enc_bih_f = (const float*)d_in[3];
    const float* enc_bhh_f = (const float*)d_in[4];
    const float* enc_Wih_b = (const float*)d_in[5];
    const float* enc_Whh_b = (const float*)d_in[6];
    const float* enc_bih_b = (const float*)d_in[7];
    const float* enc_bhh_b = (const float*)d_in[8];
    const float* dec_emb   = (const float*)d_in[9];
    const float* dec_Wih   = (const float*)d_in[10];
    const float* dec_Whh   = (const float*)d_in[11];
    const float* dec_bih   = (const float*)d_in[12];
    const float* dec_bhh   = (const float*)d_in[13];
    const float* fc_W      = (const float*)d_in[14];
    const float* fc_b      = (const float*)d_in[15];
    const int*   in_text   = (const int*)d_in[16];
    // d_in[17] in_lengths: unused by reference
    const int*   poses     = (const int*)d_in[18];
    // d_in[19] vid_indices: unused by reference
    float* out = (float*)d_out;

    // init hidden states
    zero_h<<<(Bsz * HIDD + 255) / 256, 256>>>();

    // bulk input GEMMs (off the critical serial chain)
    gemm_big<0><<<dim3(48, 128, 2), 256>>>(enc_emb, in_text,
                                           enc_Wih_f, enc_bih_f,
                                           enc_Wih_b, enc_bih_b,
                                           nullptr, H3, EMBD);
    gemm_big<1><<<dim3(48, 180, 1), 256>>>(dec_emb, poses,
                                           dec_Wih, dec_bih,
                                           nullptr, nullptr,
                                           nullptr, H3, HIDD);

    // encoder recurrence: both directions in parallel (blockIdx.z)
    for (int t = 0; t < TIN; t++)
        gru_step<<<dim3(32, 4, 2), 128>>>(0, t, enc_Whh_f, enc_bhh_f,
                                          enc_Whh_b, enc_bhh_b);

    combine_h0<<<(Bsz * HIDD + 255) / 256, 256>>>();

    // decoder recurrence
    for (int t = 0; t < TOUT; t++)
        gru_step<<<dim3(32, 4, 1), 128>>>(1, t, dec_Whh, dec_bhh,
                                          dec_Whh, dec_bhh);

    // final projection to [90,128,514]
    gemm_big<2><<<dim3(9, 180, 1), 256>>>(nullptr, nullptr,
                                          fc_W, fc_b,
                                          nullptr, nullptr,
                                          out, POSEN, HIDD);
}

// round 2
// speedup vs baseline: 1.0137x; 1.0137x over previous
#include <cuda_runtime.h>
#include <math.h>

#define Bsz   128
#define TIN   64
#define TOUT  90
#define HIDD  1024
#define H3    3072
#define EMBD  300
#define POSEN 514

// ---------------- scratch (device globals; no allocation allowed) ----------
__device__ float g_gi_enc[2][TIN * Bsz * H3];     // per-dir precomputed x@Wih^T + bih
__device__ float g_gi_dec[TOUT * Bsz * H3];       // decoder input gates
__device__ float g_h_enc[2][2][Bsz * HIDD];       // [dir][pingpong]
__device__ float g_dec_h0[Bsz * HIDD];
__device__ float g_hs[TOUT * Bsz * HIDD];         // decoder hidden states

// ---------------- bulk GEMM: C[m,n] = gather_row(m) . W[n,:] + bias[n] -----
// MODE 0: encoder input  (A row = enc_emb[in_text[b,t]], K=300, out g_gi_enc[z])
// MODE 1: decoder input  (A row = dec_emb[poses[b, max(t-1,0)]], K=1024, out g_gi_dec)
// MODE 2: final FC       (A row = g_hs[m], K=1024, N=514, out Cout)
template <int MODE>
__global__ void __launch_bounds__(256) gemm_big(
    const float* __restrict__ Aemb, const int* __restrict__ idx,
    const float* __restrict__ W0, const float* __restrict__ b0,
    const float* __restrict__ W1, const float* __restrict__ b1,
    float* __restrict__ Cout, int N, int K)
{
    const float* W    = W0;
    const float* bias = b0;
    if (MODE == 0 && blockIdx.z == 1) { W = W1; bias = b1; }

    __shared__ float As[32][68];   // As[k][m], pad keeps float4 alignment
    __shared__ float Bs[32][68];   // Bs[k][n]

    const int tid  = threadIdx.x;
    const int tx   = tid & 15;
    const int ty   = tid >> 4;
    const int lrow = tid >> 5;     // 0..7
    const int lk   = tid & 31;     // 0..31

    // precompute gathered A row pointers (8 rows per thread-group)
    const float* aptr[8];
#pragma unroll
    for (int i = 0; i < 8; i++) {
        int m = blockIdx.y * 64 + i * 8 + lrow;
        if (MODE == 0) {
            int t = m >> 7, b = m & 127;
            int tok = idx[b * TIN + t];
            aptr[i] = Aemb + (size_t)tok * EMBD;
        } else if (MODE == 1) {
            int t = m >> 7, b = m & 127;
            int ti = (t == 0) ? 0 : (t - 1);
            int pi = idx[b * TOUT + ti];
            aptr[i] = Aemb + (size_t)pi * HIDD;
        } else {
            aptr[i] = g_hs + (size_t)m * HIDD;
        }
    }

    float acc[4][4] = {};

    for (int kt = 0; kt < K; kt += 32) {
#pragma unroll
        for (int i = 0; i < 8; i++) {
            int kg = kt + lk;
            As[lk][i * 8 + lrow] = (kg < K) ? aptr[i][kg] : 0.f;
        }
#pragma unroll
        for (int i = 0; i < 8; i++) {
            int n  = blockIdx.x * 64 + i * 8 + lrow;
            int kg = kt + lk;
            float v = 0.f;
            if (n < N && kg < K) v = W[(size_t)n * K + kg];
            Bs[lk][i * 8 + lrow] = v;
        }
        __syncthreads();
#pragma unroll
        for (int kk = 0; kk < 32; kk++) {
            float4 a4 = *(const float4*)&As[kk][ty * 4];
            float4 b4 = *(const float4*)&Bs[kk][tx * 4];
            float av[4] = {a4.x, a4.y, a4.z, a4.w};
            float bv[4] = {b4.x, b4.y, b4.z, b4.w};
#pragma unroll
            for (int r = 0; r < 4; r++)
#pragma unroll
                for (int c = 0; c < 4; c++)
                    acc[r][c] += av[r] * bv[c];
        }
        __syncthreads();
    }

#pragma unroll
    for (int r = 0; r < 4; r++) {
        int m = blockIdx.y * 64 + ty * 4 + r;
#pragma unroll
        for (int c = 0; c < 4; c++) {
            int n = blockIdx.x * 64 + tx * 4 + c;
            if (n < N) {
                float v = acc[r][c] + bias[n];
                if (MODE == 0)      g_gi_enc[blockIdx.z][(size_t)m * H3 + n] = v;
                else if (MODE == 1) g_gi_dec[(size_t)m * H3 + n] = v;
                else                Cout[(size_t)m * POSEN + n] = v;
            }
        }
    }
}

// ---------------- fused recurrent step ------------------------------------
// One block computes a 32(batch) x 32(hidden) tile of h', accumulating the
// three gate chunks (r,z,n) of gh = h@Whh^T over K=1024, then applies GRU
// gate math with the precomputed gi in the epilogue.
// mode 0: encoder (blockIdx.z = direction), mode 1: decoder.
__global__ void __launch_bounds__(128) gru_step(
    int mode, int t,
    const float* __restrict__ W0, const float* __restrict__ b0,
    const float* __restrict__ W1, const float* __restrict__ b1)
{
    const float* Whh = (blockIdx.z == 1) ? W1 : W0;
    const float* bhh = (blockIdx.z == 1) ? b1 : b0;

    const float* h_in;
    float*       h_out;
    const float* gi;
    if (mode == 0) {
        int d = blockIdx.z;
        h_in  = g_h_enc[d][t & 1];
        h_out = g_h_enc[d][(t & 1) ^ 1];
        gi    = g_gi_enc[d] + (size_t)t * Bsz * H3;
    } else {
        h_in  = (t == 0) ? g_dec_h0 : (g_hs + (size_t)(t - 1) * Bsz * HIDD);
        h_out = g_hs + (size_t)t * Bsz * HIDD;
        gi    = g_gi_dec + (size_t)t * Bsz * H3;
    }

    __shared__ float As[32][36];       // As[k][m]
    __shared__ float Ws[3][32][34];    // Ws[chunk][k][n]

    const int tid  = threadIdx.x;
    const int tx   = tid & 15;         // 0..15 -> 2 cols each
    const int ty   = tid >> 4;         // 0..7  -> 4 rows each
    const int lrow = tid >> 5;         // 0..3
    const int lk   = tid & 31;
    const int m0   = blockIdx.y * 32;
    const int n0   = blockIdx.x * 32;

    float acc[3][4][2] = {};

    for (int kt = 0; kt < HIDD; kt += 32) {
#pragma unroll
        for (int i = 0; i < 8; i++) {
            int r = i * 4 + lrow;
            As[lk][r] = h_in[(size_t)(m0 + r) * HIDD + kt + lk];
        }
#pragma unroll
        for (int c = 0; c < 3; c++) {
#pragma unroll
            for (int i = 0; i < 8; i++) {
                int r  = i * 4 + lrow;
                int ng = c * HIDD + n0 + r;
                Ws[c][lk][r] = Whh[(size_t)ng * HIDD + kt + lk];
            }
        }
        __syncthreads();
#pragma unroll
        for (int kk = 0; kk < 32; kk++) {
            float4 a4 = *(const float4*)&As[kk][ty * 4];
            float2 w0 = *(const float2*)&Ws[0][kk][tx * 2];
            float2 w1 = *(const float2*)&Ws[1][kk][tx * 2];
            float2 w2 = *(const float2*)&Ws[2][kk][tx * 2];
            float av[4] = {a4.x, a4.y, a4.z, a4.w};
#pragma unroll
            for (int r = 0; r < 4; r++) {
                acc[0][r][0] += av[r] * w0.x;  acc[0][r][1] += av[r] * w0.y;
                acc[1][r][0] += av[r] * w1.x;  acc[1][r][1] += av[r] * w1.y;
                acc[2][r][0] += av[r] * w2.x;  acc[2][r][1] += av[r] * w2.y;
            }
        }
        __syncthreads();
    }

#pragma unroll
    for (int r = 0; r < 4; r++) {
        int m = m0 + ty * 4 + r;
        const float* gim = gi + (size_t)m * H3;
#pragma unroll
        for (int j = 0; j < 2; j++) {
            int jg = n0 + tx * 2 + j;
            float ghr = acc[0][r][j] + bhh[jg];
            float ghz = acc[1][r][j] + bhh[HIDD + jg];
            float ghn = acc[2][r][j] + bhh[2 * HIDD + jg];
            float rr = 1.f / (1.f + expf(-(gim[jg] + ghr)));
            float zz = 1.f / (1.f + expf(-(gim[HIDD + jg] + ghz)));
            float nn = tanhf(gim[2 * HIDD + jg] + rr * ghn);
            h_out[(size_t)m * HIDD + jg] =
                (1.f - zz) * nn + zz * h_in[(size_t)m * HIDD + jg];
        }
    }
}

// ---------------- small helpers -------------------------------------------
__global__ void zero_h()
{
    int i = blockIdx.x * blockDim.x + threadIdx.x;
    if (i < Bsz * HIDD) {
        g_h_enc[0][0][i] = 0.f;
        g_h_enc[1][0][i] = 0.f;
    }
}

__global__ void combine_h0()
{
    int i = blockIdx.x * blockDim.x + threadIdx.x;
    if (i < Bsz * HIDD)
        g_dec_h0[i] = g_h_enc[0][0][i] + g_h_enc[1][0][i];
}

// ---------------- launch ----------------------------------------------------
extern "C" void kernel_launch(void* const* d_in, const int* in_sizes, int n_in,
                              void* d_out, int out_size)
{
    const float* enc_emb   = (const float*)d_in[0];
    const float* enc_Wih_f = (const float*)d_in[1];
    const float* enc_Whh_f = (const float*)d_in[2];
    const float* enc_bih_f = (const float*)d_in[3];
    const float* enc_bhh_f = (const float*)d_in[4];
    const float* enc_Wih_b = (const float*)d_in[5];
    const float* enc_Whh_b = (const float*)d_in[6];
    const float* enc_bih_b = (const float*)d_in[7];
    const float* enc_bhh_b = (const float*)d_in[8];
    const float* dec_emb   = (const float*)d_in[9];
    const float* dec_Wih   = (const float*)d_in[10];
    const float* dec_Whh   = (const float*)d_in[11];
    const float* dec_bih   = (const float*)d_in[12];
    const float* dec_bhh   = (const float*)d_in[13];
    const float* fc_W      = (const float*)d_in[14];
    const float* fc_b      = (const float*)d_in[15];
    const int*   in_text   = (const int*)d_in[16];
    // d_in[17] in_lengths: unused by reference
    const int*   poses     = (const int*)d_in[18];
    // d_in[19] vid_indices: unused by reference
    float* out = (float*)d_out;

    // init hidden states
    zero_h<<<(Bsz * HIDD + 255) / 256, 256>>>();

    // bulk input GEMMs (off the critical serial chain)
    gemm_big<0><<<dim3(48, 128, 2), 256>>>(enc_emb, in_text,
                                           enc_Wih_f, enc_bih_f,
                                           enc_Wih_b, enc_bih_b,
                                           nullptr, H3, EMBD);
    gemm_big<1><<<dim3(48, 180, 1), 256>>>(dec_emb, poses,
                                           dec_Wih, dec_bih,
                                           nullptr, nullptr,
                                           nullptr, H3, HIDD);

    // encoder recurrence: both directions in parallel (blockIdx.z)
    for (int t = 0; t < TIN; t++)
        gru_step<<<dim3(32, 4, 2), 128>>>(0, t, enc_Whh_f, enc_bhh_f,
                                          enc_Whh_b, enc_bhh_b);

    combine_h0<<<(Bsz * HIDD + 255) / 256, 256>>>();

    // decoder recurrence
    for (int t = 0; t < TOUT; t++)
        gru_step<<<dim3(32, 4, 1), 128>>>(1, t, dec_Whh, dec_bhh,
                                          dec_Whh, dec_bhh);

    // final projection to [90,128,514]
    gemm_big<2><<<dim3(9, 180, 1), 256>>>(nullptr, nullptr,
                                          fc_W, fc_b,
                                          nullptr, nullptr,
                                          out, POSEN, HIDD);
}

// round 5
// speedup vs baseline: 1.9886x; 1.9618x over previous
#include <cuda_runtime.h>
#include <cuda_bf16.h>
#include <math.h>
#include <stdint.h>

#define HID  1024
#define H3   3072
#define VOC  3863
#define VOCP 3968
#define PON  514
#define PONP 640
#define TIN  64
#define TOUT 90
#define KP3  3072
#define KPE  960
#define KS_ENC 2
#define KS_DEC 4
#define DEPTH 4
#define ASTG 16384
#define WSTG 12288
#define SMTOT (DEPTH*(ASTG+WSTG))   // 114688 B dynamic smem

// ------------------------- device-global scratch ---------------------------
__device__ __nv_bfloat16 g_WhhI[3][H3*KP3];       // interleaved rows, [hi|lo|hi]
__device__ __nv_bfloat16 g_WihIe[2][H3*KPE];
__device__ __nv_bfloat16 g_WihId[H3*KP3];
__device__ __nv_bfloat16 g_Wfc[576*KP3];
__device__ __nv_bfloat16 g_embE[VOCP*KPE];        // [hi|hi|lo]
__device__ __nv_bfloat16 g_embD[PONP*KP3];
__device__ float g_Ue[2][(size_t)VOCP*H3];        // input-gate tables (interleaved cols)
__device__ float g_Ud[(size_t)PONP*H3];
__device__ float g_bihE[2][H3];
__device__ float g_bihD[H3];
__device__ float g_bhhI[3][H3];
__device__ __nv_bfloat16 g_hAe[2][2][128*KP3];    // encoder h split A, ping-pong
__device__ float g_hFe[2][2][128*HID];
__device__ float g_hFd[2][128*HID];
__device__ float g_d0F[128*HID];
__device__ __nv_bfloat16 g_d0A[128*KP3];
__device__ __nv_bfloat16 g_fcA[(size_t)TOUT*128*KP3];  // decoder states (split) = FC input
__device__ float g_part[2][4][32][128*96];        // [z][ks][nx][m*96+n]
__device__ int   g_cnt[2][160][32];               // fan-in counters [z][tslot][nx]

// ------------------------------ asm helpers --------------------------------
__device__ __forceinline__ uint32_t smem_u32(const void* p){
    uint32_t a;
    asm("{ .reg .u64 t; cvta.to.shared.u64 t, %1; cvt.u32.u64 %0, t; }":"=r"(a):"l"(p));
    return a;
}
#define SWZ(x) ((x) ^ (((x) >> 3) & 0x70))
#define CP16(d_, s_) asm volatile("cp.async.cg.shared.global [%0], [%1], 16;"::"r"(d_),"l"(s_))
#define CPCOMMIT()   asm volatile("cp.async.commit_group;":::"memory")
#define CPWAIT(n)    asm volatile("cp.async.wait_group %0;"::"n"(n):"memory")
#define LDSM4(r, a) \
    asm volatile("ldmatrix.sync.aligned.m8n8.x4.shared.b16 {%0,%1,%2,%3}, [%4];" \
        : "=r"((r)[0]),"=r"((r)[1]),"=r"((r)[2]),"=r"((r)[3]) : "r"(a))
#define LDSM2(r, a) \
    asm volatile("ldmatrix.sync.aligned.m8n8.x2.shared.b16 {%0,%1}, [%2];" \
        : "=r"((r)[0]),"=r"((r)[1]) : "r"(a))
#define MMA16816(d, a, b) \
    asm volatile("mma.sync.aligned.m16n8k16.row.col.f32.bf16.bf16.f32 " \
        "{%0,%1,%2,%3}, {%4,%5,%6,%7}, {%8,%9}, {%0,%1,%2,%3};" \
        : "+f"((d)[0]),"+f"((d)[1]),"+f"((d)[2]),"+f"((d)[3]) \
        : "r"((a)[0]),"r"((a)[1]),"r"((a)[2]),"r"((a)[3]),"r"((b)[0]),"r"((b)[1]))

// ------------------------------ prep kernels -------------------------------
// Weight split-interleave. Interleaved row nr = x*96 + g*32 + u  <-  src g*HID + x*32 + u.
// K' layout per row: [hi | lo | hi].
__global__ void prep_w(const float* __restrict__ src, const float* __restrict__ bs, int which)
{
    __nv_bfloat16* dst; float* bd; int Nrows=H3, realR=H3, K=HID, Kpad=HID, inter=1;
    switch(which){
        case 0: dst=g_WihIe[0]; bd=g_bihE[0]; K=300; Kpad=320; break;
        case 1: dst=g_WihIe[1]; bd=g_bihE[1]; K=300; Kpad=320; break;
        case 2: dst=g_WihId;    bd=g_bihD;    break;
        case 3: dst=g_WhhI[0];  bd=g_bhhI[0]; break;
        case 4: dst=g_WhhI[1];  bd=g_bhhI[1]; break;
        case 5: dst=g_WhhI[2];  bd=g_bhhI[2]; break;
        default: dst=g_Wfc; bd=0; Nrows=576; realR=PON; inter=0; break;
    }
    int KP = 3*Kpad;
    long total = (long)Nrows*KP;
    for (long o=(long)blockIdx.x*blockDim.x+threadIdx.x; o<total;
         o += (long)gridDim.x*blockDim.x){
        int nr=(int)(o/KP), kq=(int)(o%KP), seg=kq/Kpad, kk=kq%Kpad;
        int gr;
        if (inter){ int x=nr/96, rem=nr%96, g=rem/32, u=rem%32; gr=g*HID + x*32 + u; }
        else gr = nr;
        float v = (kk<K && gr<realR) ? src[(size_t)gr*K+kk] : 0.f;
        __nv_bfloat16 hi = __float2bfloat16(v);
        dst[o] = (seg==1) ? __float2bfloat16(v - __bfloat162float(hi)) : hi;
        if (kq==0 && bd) bd[nr] = (gr<realR) ? bs[gr] : 0.f;
    }
}
// Embedding split: [hi | hi | lo]
__global__ void prep_a(const float* __restrict__ src, int which)
{
    __nv_bfloat16* dst; int R, realR, K, Kpad;
    if (which==0){ dst=g_embE; R=VOCP; realR=VOC; K=300; Kpad=320; }
    else         { dst=g_embD; R=PONP; realR=PON; K=HID; Kpad=HID; }
    int KP = 3*Kpad;
    long total = (long)R*KP;
    for (long o=(long)blockIdx.x*blockDim.x+threadIdx.x; o<total;
         o += (long)gridDim.x*blockDim.x){
        int r=(int)(o/KP), kq=(int)(o%KP), seg=kq/Kpad, kk=kq%Kpad;
        int gr = r<realR ? r : 0;
        float v = kk<K ? src[(size_t)gr*K+kk] : 0.f;
        __nv_bfloat16 hi = __float2bfloat16(v);
        dst[o] = (seg==2) ? __float2bfloat16(v - __bfloat162float(hi)) : hi;
    }
}
__global__ void init_h(){
    int i = blockIdx.x*blockDim.x+threadIdx.x;
    if (i < 128*HID){ g_hFe[0][0][i]=0.f; g_hFe[1][0][i]=0.f; }
    if (i < 128*KP3){
        g_hAe[0][0][i]=__float2bfloat16(0.f);
        g_hAe[1][0][i]=__float2bfloat16(0.f);
    }
    if (i < 2*160*32) ((int*)g_cnt)[i] = 0;
}
__global__ void combine(){
    int i = blockIdx.x*blockDim.x+threadIdx.x;
    if (i >= 128*HID) return;
    int m = i/HID, c = i%HID;
    float h = g_hFe[0][0][i] + g_hFe[1][0][i];
    g_d0F[i] = h;
    __nv_bfloat16 hh = __float2bfloat16(h);
    g_d0A[(size_t)m*KP3 + c]         = hh;
    g_d0A[(size_t)m*KP3 + HID + c]   = hh;
    g_d0A[(size_t)m*KP3 + 2*HID + c] = __float2bfloat16(h - __bfloat162float(hh));
}

// --------------------------- unified HMMA GEMM -----------------------------
// CTA tile: M=128, N=96, stage K=64. 256 threads, warp tile 64x24.
// MODE 0: U_enc = embE . WihIe[z]^T + bihE     grid(32, 31, 2)
// MODE 1: U_dec = embD . WihId^T + bihD        grid(32, 5, 1)
// MODE 2: encoder GRU step (y=ks, z=dir)       grid(32, KS_ENC, 2)
// MODE 3: decoder GRU step (y=ks)              grid(32, KS_DEC, 1)
// MODE 4: FC out                               grid(6, 90, 1)
template<int MODE>
__global__ void __launch_bounds__(256) gk(int t, const int* __restrict__ idx,
                                          const float* __restrict__ fcb,
                                          float* __restrict__ outp)
{
    constexpr int KS  = (MODE==2)?KS_ENC:(MODE==3)?KS_DEC:1;
    constexpr int KPT = (MODE==0)?KPE:KP3;
    constexpr int KCH = KPT/KS;
    constexpr int SK  = KCH/64;
    const int nx = blockIdx.x;
    const int by = blockIdx.y;
    const int z  = blockIdx.z;
    const int ks = (MODE==2||MODE==3)? by : 0;
    const int my = (MODE==2||MODE==3)? 0  : by;

    const int tid = threadIdx.x;
    const int w = tid>>5, lane = tid&31;
    const int wm = w&1, wn = w>>1;

    extern __shared__ __align__(16) char sm[];
    uint32_t smA32 = smem_u32(sm);
    uint32_t smW32 = smA32 + DEPTH*ASTG;

    // per-thread cp.async source/dest
    const char* asrc[4]; uint32_t adst[4];
    const char* wsrc[3]; uint32_t wdst[3];
    const size_t kb0 = (size_t)ks*KCH*2;
#pragma unroll
    for (int i=0;i<4;i++){
        int id = tid + 256*i, r = id>>3, c = id&7;
        const __nv_bfloat16* p;
        if (MODE==0){ int v=my*128+r; if(v>=VOC) v=0; p=g_embE+(size_t)v*KPE; }
        else if (MODE==1){ int v=my*128+r; if(v>=PON) v=0; p=g_embD+(size_t)v*KP3; }
        else if (MODE==2){ p=g_hAe[z][t&1]+(size_t)r*KP3; }
        else if (MODE==3){ p=(t==0? g_d0A : g_fcA+(size_t)(t-1)*128*KP3)+(size_t)r*KP3; }
        else { p=g_fcA+(size_t)(my*128+r)*KP3; }
        asrc[i] = (const char*)p + kb0 + c*16;
        adst[i] = SWZ((uint32_t)(r*128 + c*16));
    }
    {
        const __nv_bfloat16* Wb = (MODE==0)?g_WihIe[z]:(MODE==1)?g_WihId:
                                  (MODE==2)?g_WhhI[z]:(MODE==3)?g_WhhI[2]:g_Wfc;
#pragma unroll
        for (int i=0;i<3;i++){
            int id = tid + 256*i, r = id>>3, c = id&7;
            wsrc[i] = (const char*)(Wb + (size_t)(nx*96+r)*KPT) + kb0 + c*16;
            wdst[i] = SWZ((uint32_t)(r*128 + c*16));
        }
    }

    auto load_stage = [&](int s){
        int b = s & (DEPTH-1);
        uint32_t dA = smA32 + b*ASTG, dW = smW32 + b*WSTG;
        size_t off = (size_t)s*128;
#pragma unroll
        for (int i=0;i<4;i++) CP16(dA+adst[i], asrc[i]+off);
#pragma unroll
        for (int i=0;i<3;i++) CP16(dW+wdst[i], wsrc[i]+off);
        CPCOMMIT();
    };

    float acc[4][3][4];
#pragma unroll
    for (int a=0;a<4;a++)
#pragma unroll
        for (int b=0;b<3;b++)
#pragma unroll
            for (int c=0;c<4;c++) acc[a][b][c]=0.f;

    load_stage(0); load_stage(1); load_stage(2);

    const int arow_l = wm*64 + (lane&15);
    const int a_kb   = (lane>>4)*16;
    const int brow_l = wn*24 + (lane&7);
    const int b_kb   = ((lane>>3)&1)*16;

    for (int s=0; s<SK; s++){
        if (s < SK-2)      CPWAIT(2);
        else if (s==SK-2)  CPWAIT(1);
        else               CPWAIT(0);
        __syncthreads();
        if (s+3 < SK) load_stage(s+3);
        int b = s & (DEPTH-1);
        uint32_t aB = smA32 + b*ASTG, wB = smW32 + b*WSTG;
#pragma unroll
        for (int kk=0; kk<4; kk++){
            uint32_t aF[4][4], bF[3][2];
#pragma unroll
            for (int mi=0; mi<4; mi++)
                LDSM4(aF[mi], aB + SWZ((uint32_t)((arow_l+mi*16)*128 + kk*32 + a_kb)));
#pragma unroll
            for (int ni=0; ni<3; ni++)
                LDSM2(bF[ni], wB + SWZ((uint32_t)((brow_l+ni*8)*128 + kk*32 + b_kb)));
#pragma unroll
            for (int mi=0;mi<4;mi++)
#pragma unroll
                for (int ni=0;ni<3;ni++)
                    MMA16816(acc[mi][ni], aF[mi], bF[ni]);
        }
        __syncthreads();
    }

    const int gr = lane>>2, gc = (lane&3)*2;

    if (MODE==0 || MODE==1){
        const float* bi = (MODE==0)? g_bihE[z] : g_bihD;
        float* Ub = (MODE==0)? g_Ue[z] : g_Ud;
        const int vreal = (MODE==0)? VOC : PON;
#pragma unroll
        for (int mi=0;mi<4;mi++)
#pragma unroll
            for (int h=0;h<2;h++){
                int m = wm*64+mi*16+gr+h*8;
                int v = my*128+m;
                if (v < vreal){
#pragma unroll
                    for (int ni=0;ni<3;ni++){
                        int n = nx*96 + wn*24 + ni*8 + gc;
                        float2 val = { acc[mi][ni][h*2+0]+bi[n], acc[mi][ni][h*2+1]+bi[n+1] };
                        *(float2*)&Ub[(size_t)v*H3 + n] = val;
                    }
                }
            }
        return;
    }
    if (MODE==4){
#pragma unroll
        for (int mi=0;mi<4;mi++)
#pragma unroll
            for (int h=0;h<2;h++){
                int mm = my*128 + wm*64+mi*16+gr+h*8;
#pragma unroll
                for (int ni=0;ni<3;ni++){
                    int n = nx*96 + wn*24 + ni*8 + gc;
                    if (n < PON){
                        float2 val = { acc[mi][ni][h*2+0]+fcb[n], acc[mi][ni][h*2+1]+fcb[n+1] };
                        *(float2*)&outp[(size_t)mm*PON + n] = val;
                    }
                }
            }
        return;
    }

    // ---- step modes: store partial, per-nx fan-in, fused GRU epilogue ----
    {
        float* pb = g_part[z][ks][nx];
#pragma unroll
        for (int mi=0;mi<4;mi++)
#pragma unroll
            for (int h=0;h<2;h++){
                int m = wm*64+mi*16+gr+h*8;
#pragma unroll
                for (int ni=0;ni<3;ni++){
                    int n = wn*24 + ni*8 + gc;
                    float2 val = { acc[mi][ni][h*2+0], acc[mi][ni][h*2+1] };
                    *(float2*)&pb[m*96 + n] = val;
                }
            }
    }
    __threadfence();
    __syncthreads();
    __shared__ int s_win;
    if (tid==0){
        int slot = (MODE==2)? t : TIN + t;
        int old = atomicAdd(&g_cnt[z][slot][nx], 1);
        s_win = (old == KS-1);
    }
    __syncthreads();
    if (!s_win) return;
    __threadfence();

    const float* U; const float* bh; const float* hin; float* hout; __nv_bfloat16* hA;
    if (MODE==2){
        U = g_Ue[z]; bh = g_bhhI[z];
        hin = g_hFe[z][t&1]; hout = g_hFe[z][(t&1)^1]; hA = g_hAe[z][(t&1)^1];
    } else {
        U = g_Ud; bh = g_bhhI[2];
        hin = t ? g_hFd[(t-1)&1] : g_d0F;
        hout = g_hFd[t&1];
        hA = g_fcA + (size_t)t*128*KP3;
    }
    const int u  = tid & 31;
    const int xu = nx*32 + u;
    const float br = bh[nx*96+u], bz = bh[nx*96+32+u], bn = bh[nx*96+64+u];
#pragma unroll 4
    for (int i=0;i<16;i++){
        int m = (tid>>5) + i*8;
        int tok = (MODE==2)? idx[m*TIN + t] : idx[m*TOUT + (t? t-1:0)];
        const float* Urow = U + (size_t)tok*H3 + nx*96;
        float sr=0.f, sz=0.f, sn=0.f;
#pragma unroll
        for (int k2=0;k2<KS;k2++){
            const float* pp = g_part[z][k2][nx] + m*96;
            sr += __ldcg(pp+u); sz += __ldcg(pp+32+u); sn += __ldcg(pp+64+u);
        }
        float rr = 1.f/(1.f+expf(-(Urow[u]      + sr + br)));
        float zz = 1.f/(1.f+expf(-(Urow[32+u]   + sz + bz)));
        float nn = tanhf(Urow[64+u] + rr*(sn + bn));
        float h  = (1.f-zz)*nn + zz*hin[(size_t)m*HID + xu];
        hout[(size_t)m*HID + xu] = h;
        __nv_bfloat16 hh = __float2bfloat16(h);
        hA[(size_t)m*KP3 + xu]         = hh;
        hA[(size_t)m*KP3 + HID + xu]   = hh;
        hA[(size_t)m*KP3 + 2*HID + xu] = __float2bfloat16(h - __bfloat162float(hh));
    }
}

// ------------------------------- launch ------------------------------------
extern "C" void kernel_launch(void* const* d_in, const int* in_sizes, int n_in,
                              void* d_out, int out_size)
{
    const float* enc_emb   = (const float*)d_in[0];
    const float* enc_Wih_f = (const float*)d_in[1];
    const float* enc_Whh_f = (const float*)d_in[2];
    const float* enc_bih_f = (const float*)d_in[3];
    const float* enc_bhh_f = (const float*)d_in[4];
    const float* enc_Wih_b = (const float*)d_in[5];
    const float* enc_Whh_b = (const float*)d_in[6];
    const float* enc_bih_b = (const float*)d_in[7];
    const float* enc_bhh_b = (const float*)d_in[8];
    const float* dec_emb   = (const float*)d_in[9];
    const float* dec_Wih   = (const float*)d_in[10];
    const float* dec_Whh   = (const float*)d_in[11];
    const float* dec_bih   = (const float*)d_in[12];
    const float* dec_bhh   = (const float*)d_in[13];
    const float* fc_W      = (const float*)d_in[14];
    const float* fc_b      = (const float*)d_in[15];
    const int*   in_text   = (const int*)d_in[16];
    const int*   poses     = (const int*)d_in[18];
    float* out = (float*)d_out;

    cudaFuncSetAttribute(gk<0>, cudaFuncAttributeMaxDynamicSharedMemorySize, SMTOT);
    cudaFuncSetAttribute(gk<1>, cudaFuncAttributeMaxDynamicSharedMemorySize, SMTOT);
    cudaFuncSetAttribute(gk<2>, cudaFuncAttributeMaxDynamicSharedMemorySize, SMTOT);
    cudaFuncSetAttribute(gk<3>, cudaFuncAttributeMaxDynamicSharedMemorySize, SMTOT);
    cudaFuncSetAttribute(gk<4>, cudaFuncAttributeMaxDynamicSharedMemorySize, SMTOT);

    prep_a<<<512,256>>>(enc_emb, 0);
    prep_a<<<512,256>>>(dec_emb, 1);
    prep_w<<<512,256>>>(enc_Wih_f, enc_bih_f, 0);
    prep_w<<<512,256>>>(enc_Wih_b, enc_bih_b, 1);
    prep_w<<<512,256>>>(dec_Wih,   dec_bih,   2);
    prep_w<<<512,256>>>(enc_Whh_f, enc_bhh_f, 3);
    prep_w<<<512,256>>>(enc_Whh_b, enc_bhh_b, 4);
    prep_w<<<512,256>>>(dec_Whh,   dec_bhh,   5);
    prep_w<<<512,256>>>(fc_W,      nullptr,   6);
    init_h<<<(128*KP3+255)/256,256>>>();

    gk<0><<<dim3(32,31,2),256,SMTOT>>>(0, nullptr, nullptr, nullptr);
    gk<1><<<dim3(32,5,1), 256,SMTOT>>>(0, nullptr, nullptr, nullptr);

    for (int t=0;t<TIN;t++)
        gk<2><<<dim3(32,KS_ENC,2),256,SMTOT>>>(t, in_text, nullptr, nullptr);
    combine<<<(128*HID+255)/256,256>>>();
    for (int t=0;t<TOUT;t++)
        gk<3><<<dim3(32,KS_DEC,1),256,SMTOT>>>(t, poses, nullptr, nullptr);

    gk<4><<<dim3(6,90,1),256,SMTOT>>>(0, nullptr, fc_b, out);
}

// round 6
// speedup vs baseline: 3.0902x; 1.5540x over previous
#include <cuda_runtime.h>
#include <cuda_bf16.h>
#include <math.h>
#include <stdint.h>

#define HID  1024
#define H3   3072
#define VOC  3863
#define VOCP 3968
#define PON  514
#define PONP 640
#define TIN  64
#define TOUT 90
#define KP3  3072
#define KPE  960
#define KS_ENC 2
#define KS_DEC 4
#define DEPTH 4
#define ASTG 16384
#define WSTG 12288
#define SMTOT (DEPTH*(ASTG+WSTG))   // 114688 B dynamic smem

// ------------------------- device-global scratch ---------------------------
__device__ __nv_bfloat16 g_WhhI[3][H3*KP3];       // interleaved rows, [hi|lo|hi]
__device__ __nv_bfloat16 g_WihIe[2][H3*KPE];
__device__ __nv_bfloat16 g_WihId[H3*KP3];
__device__ __nv_bfloat16 g_Wfc[576*KP3];
__device__ __nv_bfloat16 g_embE[VOCP*KPE];        // [hi|hi|lo]
__device__ __nv_bfloat16 g_embD[PONP*KP3];
__device__ float g_Ue[2][(size_t)VOCP*H3];        // input-gate tables (interleaved cols)
__device__ float g_Ud[(size_t)PONP*H3];
__device__ float g_bihE[2][H3];
__device__ float g_bihD[H3];
__device__ float g_bhhI[3][H3];
__device__ __nv_bfloat16 g_hAe[2][2][128*KP3];    // encoder h split A, ping-pong
__device__ float g_hFe[2][2][128*HID];
__device__ float g_hFd[2][128*HID];
__device__ float g_d0F[128*HID];
__device__ __nv_bfloat16 g_d0A[128*KP3];
__device__ __nv_bfloat16 g_fcA[(size_t)TOUT*128*KP3];  // decoder states (split) = FC input
__device__ float g_part[2][4][32][128*96];        // [z][ks][nx][m*96+n]
__device__ int   g_barE, g_barD;                  // grid barriers (monotonic)

// ------------------------------ asm helpers --------------------------------
__device__ __forceinline__ uint32_t smem_u32(const void* p){
    uint32_t a;
    asm("{ .reg .u64 t; cvta.to.shared.u64 t, %1; cvt.u32.u64 %0, t; }":"=r"(a):"l"(p));
    return a;
}
#define SWZ(x) ((x) ^ (((x) >> 3) & 0x70))
#define CP16(d_, s_) asm volatile("cp.async.cg.shared.global [%0], [%1], 16;"::"r"(d_),"l"(s_))
#define CPCOMMIT()   asm volatile("cp.async.commit_group;":::"memory")
#define CPWAIT(n)    asm volatile("cp.async.wait_group %0;"::"n"(n):"memory")
#define LDSM4(r, a) \
    asm volatile("ldmatrix.sync.aligned.m8n8.x4.shared.b16 {%0,%1,%2,%3}, [%4];" \
        : "=r"((r)[0]),"=r"((r)[1]),"=r"((r)[2]),"=r"((r)[3]) : "r"(a))
#define LDSM2(r, a) \
    asm volatile("ldmatrix.sync.aligned.m8n8.x2.shared.b16 {%0,%1}, [%2];" \
        : "=r"((r)[0]),"=r"((r)[1]) : "r"(a))
#define MMA16816(d, a, b) \
    asm volatile("mma.sync.aligned.m16n8k16.row.col.f32.bf16.bf16.f32 " \
        "{%0,%1,%2,%3}, {%4,%5,%6,%7}, {%8,%9}, {%0,%1,%2,%3};" \
        : "+f"((d)[0]),"+f"((d)[1]),"+f"((d)[2]),"+f"((d)[3]) \
        : "r"((a)[0]),"r"((a)[1]),"r"((a)[2]),"r"((a)[3]),"r"((b)[0]),"r"((b)[1]))

// grid-wide barrier: monotonic counter, fence + add + volatile spin
__device__ __forceinline__ void bar_sync(int* bar, int target)
{
    __threadfence();
    __syncthreads();
    if (threadIdx.x == 0){
        atomicAdd(bar, 1);
        while (*(volatile int*)bar < target)
            asm volatile("nanosleep.u32 64;");
        __threadfence();
    }
    __syncthreads();
}

// ------------------------------ prep kernels -------------------------------
// Weight split-interleave. Interleaved row nr = x*96 + g*32 + u <- src g*HID + x*32 + u.
// K' layout: [hi | lo | hi]. which = blockIdx.y.
__global__ void prep_w(const float* s0,const float* b0,const float* s1,const float* b1,
                       const float* s2,const float* b2,const float* s3,const float* b3,
                       const float* s4,const float* b4,const float* s5,const float* b5,
                       const float* s6)
{
    int which = blockIdx.y;
    const float* src; const float* bs = nullptr;
    __nv_bfloat16* dst; float* bd = nullptr;
    int Nrows=H3, realR=H3, K=HID, Kpad=HID, inter=1;
    switch(which){
        case 0: src=s0; bs=b0; dst=g_WihIe[0]; bd=g_bihE[0]; K=300; Kpad=320; break;
        case 1: src=s1; bs=b1; dst=g_WihIe[1]; bd=g_bihE[1]; K=300; Kpad=320; break;
        case 2: src=s2; bs=b2; dst=g_WihId;    bd=g_bihD;    break;
        case 3: src=s3; bs=b3; dst=g_WhhI[0];  bd=g_bhhI[0]; break;
        case 4: src=s4; bs=b4; dst=g_WhhI[1];  bd=g_bhhI[1]; break;
        case 5: src=s5; bs=b5; dst=g_WhhI[2];  bd=g_bhhI[2]; break;
        default: src=s6; dst=g_Wfc; Nrows=576; realR=PON; inter=0; break;
    }
    int KP = 3*Kpad;
    long total = (long)Nrows*KP;
    for (long o=(long)blockIdx.x*blockDim.x+threadIdx.x; o<total;
         o += (long)gridDim.x*blockDim.x){
        int nr=(int)(o/KP), kq=(int)(o%KP), seg=kq/Kpad, kk=kq%Kpad;
        int gr;
        if (inter){ int x=nr/96, rem=nr%96, g=rem/32, u=rem%32; gr=g*HID + x*32 + u; }
        else gr = nr;
        float v = (kk<K && gr<realR) ? src[(size_t)gr*K+kk] : 0.f;
        __nv_bfloat16 hi = __float2bfloat16(v);
        dst[o] = (seg==1) ? __float2bfloat16(v - __bfloat162float(hi)) : hi;
        if (kq==0 && bd) bd[nr] = (gr<realR) ? bs[gr] : 0.f;
    }
}
// Embedding split: [hi | hi | lo]. which = blockIdx.y.
__global__ void prep_a(const float* srcE, const float* srcD)
{
    int which = blockIdx.y;
    const float* src; __nv_bfloat16* dst; int R, realR, K, Kpad;
    if (which==0){ src=srcE; dst=g_embE; R=VOCP; realR=VOC; K=300; Kpad=320; }
    else         { src=srcD; dst=g_embD; R=PONP; realR=PON; K=HID; Kpad=HID; }
    int KP = 3*Kpad;
    long total = (long)R*KP;
    for (long o=(long)blockIdx.x*blockDim.x+threadIdx.x; o<total;
         o += (long)gridDim.x*blockDim.x){
        int r=(int)(o/KP), kq=(int)(o%KP), seg=kq/Kpad, kk=kq%Kpad;
        int gr = r<realR ? r : 0;
        float v = kk<K ? src[(size_t)gr*K+kk] : 0.f;
        __nv_bfloat16 hi = __float2bfloat16(v);
        dst[o] = (seg==2) ? __float2bfloat16(v - __bfloat162float(hi)) : hi;
    }
}
__global__ void init_h(){
    int i = blockIdx.x*blockDim.x+threadIdx.x;
    if (i < 128*HID){ g_hFe[0][0][i]=0.f; g_hFe[1][0][i]=0.f; }
    if (i < 128*KP3){
        g_hAe[0][0][i]=__float2bfloat16(0.f);
        g_hAe[1][0][i]=__float2bfloat16(0.f);
    }
    if (i == 0){ g_barE = 0; g_barD = 0; }
}
__global__ void combine(){
    int i = blockIdx.x*blockDim.x+threadIdx.x;
    if (i >= 128*HID) return;
    int m = i/HID, c = i%HID;
    float h = g_hFe[0][0][i] + g_hFe[1][0][i];
    g_d0F[i] = h;
    __nv_bfloat16 hh = __float2bfloat16(h);
    g_d0A[(size_t)m*KP3 + c]         = hh;
    g_d0A[(size_t)m*KP3 + HID + c]   = hh;
    g_d0A[(size_t)m*KP3 + 2*HID + c] = __float2bfloat16(h - __bfloat162float(hh));
}

// ----------------------------- MMA core ------------------------------------
// CTA tile M=128, N=96, stage K=64; 256 threads, warp tile 64x24, 4-deep cp.async.
template<int SK>
__device__ __forceinline__ void mma_core(uint32_t smA32, uint32_t smW32,
    const char* const* asrc, const uint32_t* adst,
    const char* const* wsrc, const uint32_t* wdst,
    int arow_l, int a_kb, int brow_l, int b_kb, float (&acc)[4][3][4])
{
#pragma unroll
    for (int a=0;a<4;a++)
#pragma unroll
        for (int b=0;b<3;b++)
#pragma unroll
            for (int c=0;c<4;c++) acc[a][b][c]=0.f;

    auto load_stage = [&](int s){
        int b = s & (DEPTH-1);
        uint32_t dA = smA32 + b*ASTG, dW = smW32 + b*WSTG;
        size_t off = (size_t)s*128;
#pragma unroll
        for (int i=0;i<4;i++) CP16(dA+adst[i], asrc[i]+off);
#pragma unroll
        for (int i=0;i<3;i++) CP16(dW+wdst[i], wsrc[i]+off);
        CPCOMMIT();
    };
    load_stage(0); load_stage(1); load_stage(2);

    for (int s=0; s<SK; s++){
        if (s < SK-2)      CPWAIT(2);
        else if (s==SK-2)  CPWAIT(1);
        else               CPWAIT(0);
        __syncthreads();
        if (s+3 < SK) load_stage(s+3);
        int b = s & (DEPTH-1);
        uint32_t aB = smA32 + b*ASTG, wB = smW32 + b*WSTG;
#pragma unroll
        for (int kk=0; kk<4; kk++){
            uint32_t aF[4][4], bF[3][2];
#pragma unroll
            for (int mi=0; mi<4; mi++)
                LDSM4(aF[mi], aB + SWZ((uint32_t)((arow_l+mi*16)*128 + kk*32 + a_kb)));
#pragma unroll
            for (int ni=0; ni<3; ni++)
                LDSM2(bF[ni], wB + SWZ((uint32_t)((brow_l+ni*8)*128 + kk*32 + b_kb)));
#pragma unroll
            for (int mi=0;mi<4;mi++)
#pragma unroll
                for (int ni=0;ni<3;ni++)
                    MMA16816(acc[mi][ni], aF[mi], bF[ni]);
        }
        __syncthreads();
    }
}

// --------------------------- bulk HMMA GEMM --------------------------------
// MODE 0: U_enc = embE . WihIe[z]^T + bihE     grid(32, 31, 2)
// MODE 1: U_dec = embD . WihId^T + bihD        grid(32, 5, 1)
// MODE 4: FC out                               grid(6, 90, 1)
template<int MODE>
__global__ void __launch_bounds__(256) gk(const float* __restrict__ fcb,
                                          float* __restrict__ outp)
{
    constexpr int KPT = (MODE==0)?KPE:KP3;
    constexpr int SK  = KPT/64;
    const int nx = blockIdx.x, my = blockIdx.y, z = blockIdx.z;
    const int tid = threadIdx.x;
    const int w = tid>>5, lane = tid&31;
    const int wm = w&1, wn = w>>1;

    extern __shared__ __align__(16) char sm[];
    uint32_t smA32 = smem_u32(sm);
    uint32_t smW32 = smA32 + DEPTH*ASTG;

    const char* asrc[4]; uint32_t adst[4];
    const char* wsrc[3]; uint32_t wdst[3];
#pragma unroll
    for (int i=0;i<4;i++){
        int id = tid + 256*i, r = id>>3, c = id&7;
        const __nv_bfloat16* p;
        if (MODE==0){ int v=my*128+r; if(v>=VOC) v=0; p=g_embE+(size_t)v*KPE; }
        else if (MODE==1){ int v=my*128+r; if(v>=PON) v=0; p=g_embD+(size_t)v*KP3; }
        else { p=g_fcA+(size_t)(my*128+r)*KP3; }
        asrc[i] = (const char*)p + c*16;
        adst[i] = SWZ((uint32_t)(r*128 + c*16));
    }
    {
        const __nv_bfloat16* Wb = (MODE==0)?g_WihIe[z]:(MODE==1)?g_WihId:g_Wfc;
#pragma unroll
        for (int i=0;i<3;i++){
            int id = tid + 256*i, r = id>>3, c = id&7;
            wsrc[i] = (const char*)(Wb + (size_t)(nx*96+r)*KPT) + c*16;
            wdst[i] = SWZ((uint32_t)(r*128 + c*16));
        }
    }
    const int arow_l = wm*64 + (lane&15);
    const int a_kb   = (lane>>4)*16;
    const int brow_l = wn*24 + (lane&7);
    const int b_kb   = ((lane>>3)&1)*16;

    float acc[4][3][4];
    mma_core<SK>(smA32, smW32, asrc, adst, wsrc, wdst, arow_l, a_kb, brow_l, b_kb, acc);

    const int gr = lane>>2, gc = (lane&3)*2;
    if (MODE==0 || MODE==1){
        const float* bi = (MODE==0)? g_bihE[z] : g_bihD;
        float* Ub = (MODE==0)? g_Ue[z] : g_Ud;
        const int vreal = (MODE==0)? VOC : PON;
#pragma unroll
        for (int mi=0;mi<4;mi++)
#pragma unroll
            for (int h=0;h<2;h++){
                int m = wm*64+mi*16+gr+h*8;
                int v = my*128+m;
                if (v < vreal){
#pragma unroll
                    for (int ni=0;ni<3;ni++){
                        int n = nx*96 + wn*24 + ni*8 + gc;
                        float2 val = { acc[mi][ni][h*2+0]+bi[n], acc[mi][ni][h*2+1]+bi[n+1] };
                        *(float2*)&Ub[(size_t)v*H3 + n] = val;
                    }
                }
            }
    } else {
#pragma unroll
        for (int mi=0;mi<4;mi++)
#pragma unroll
            for (int h=0;h<2;h++){
                int mm = my*128 + wm*64+mi*16+gr+h*8;
#pragma unroll
                for (int ni=0;ni<3;ni++){
                    int n = nx*96 + wn*24 + ni*8 + gc;
                    if (n < PON){
                        float2 val = { acc[mi][ni][h*2+0]+fcb[n], acc[mi][ni][h*2+1]+fcb[n+1] };
                        *(float2*)&outp[(size_t)mm*PON + n] = val;
                    }
                }
            }
    }
}

// ---------------------- persistent recurrent kernels -----------------------
__global__ void __launch_bounds__(256) enc_run(const int* __restrict__ idx)
{
    const int cta = blockIdx.x;                 // 128 CTAs
    const int nx = cta & 31, ks = (cta>>5)&1, z = cta>>6;
    const int tid = threadIdx.x, w = tid>>5, lane = tid&31, wm = w&1, wn = w>>1;
    extern __shared__ __align__(16) char sm[];
    uint32_t smA32 = smem_u32(sm), smW32 = smA32 + DEPTH*ASTG;
    constexpr int KCH = KP3/KS_ENC;             // 1536
    constexpr int SK  = KCH/64;                 // 24
    const size_t kb0 = (size_t)ks*KCH*2;

    const char* wsrc[3]; uint32_t wdst[3];
#pragma unroll
    for (int i=0;i<3;i++){
        int id=tid+256*i, r=id>>3, c=id&7;
        wsrc[i] = (const char*)(g_WhhI[z] + (size_t)(nx*96+r)*KP3) + kb0 + c*16;
        wdst[i] = SWZ((uint32_t)(r*128+c*16));
    }
    size_t aoff[4]; uint32_t adst[4];
#pragma unroll
    for (int i=0;i<4;i++){
        int id=tid+256*i, r=id>>3, c=id&7;
        aoff[i] = (size_t)r*KP3*2 + kb0 + c*16;
        adst[i] = SWZ((uint32_t)(r*128+c*16));
    }
    const int arow_l = wm*64 + (lane&15);
    const int a_kb   = (lane>>4)*16;
    const int brow_l = wn*24 + (lane&7);
    const int b_kb   = ((lane>>3)&1)*16;
    const int gr = lane>>2, gc = (lane&3)*2;

    const int u = lane, xu = nx*32+u;
    const float br = g_bhhI[z][nx*96+u];
    const float bz = g_bhhI[z][nx*96+32+u];
    const float bn = g_bhhI[z][nx*96+64+u];
    const float* U = g_Ue[z];
    float* pb = g_part[z][ks][nx];

    for (int t=0; t<TIN; t++){
        const char* abase = (const char*)g_hAe[z][t&1];
        const char* asrc[4];
#pragma unroll
        for (int i=0;i<4;i++) asrc[i] = abase + aoff[i];
        float acc[4][3][4];
        mma_core<SK>(smA32, smW32, asrc, adst, wsrc, wdst, arow_l, a_kb, brow_l, b_kb, acc);
#pragma unroll
        for (int mi=0;mi<4;mi++)
#pragma unroll
            for (int h=0;h<2;h++){
                int m = wm*64+mi*16+gr+h*8;
#pragma unroll
                for (int ni=0;ni<3;ni++){
                    int n = wn*24+ni*8+gc;
                    float2 v = { acc[mi][ni][h*2], acc[mi][ni][h*2+1] };
                    *(float2*)&pb[m*96+n] = v;
                }
            }
        bar_sync(&g_barE, 128*(2*t+1));
        // distributed epilogue: this CTA does m in [ks*64, ks*64+64), u = lane
        const float* hin  = g_hFe[z][t&1];
        float* hout = g_hFe[z][(t&1)^1];
        __nv_bfloat16* hA = g_hAe[z][(t&1)^1];
#pragma unroll
        for (int i=0;i<8;i++){
            int m = ks*64 + (tid>>5) + i*8;
            int tok = idx[m*TIN + t];
            const float* Urow = U + (size_t)tok*H3 + nx*96;
            const float* p0 = g_part[z][0][nx] + m*96;
            const float* p1 = g_part[z][1][nx] + m*96;
            float sr = p0[u]+p1[u], sz = p0[32+u]+p1[32+u], sn = p0[64+u]+p1[64+u];
            float rr = 1.f/(1.f+expf(-(Urow[u]    + sr + br)));
            float zz = 1.f/(1.f+expf(-(Urow[32+u] + sz + bz)));
            float nn = tanhf(Urow[64+u] + rr*(sn + bn));
            float h  = (1.f-zz)*nn + zz*hin[(size_t)m*HID + xu];
            hout[(size_t)m*HID + xu] = h;
            __nv_bfloat16 hh = __float2bfloat16(h);
            hA[(size_t)m*KP3 + xu]         = hh;
            hA[(size_t)m*KP3 + HID + xu]   = hh;
            hA[(size_t)m*KP3 + 2*HID + xu] = __float2bfloat16(h - __bfloat162float(hh));
        }
        bar_sync(&g_barE, 128*(2*t+2));
    }
}

__global__ void __launch_bounds__(256) dec_run(const int* __restrict__ idx)
{
    const int cta = blockIdx.x;                 // 128 CTAs
    const int nx = cta & 31, ks = cta>>5;       // ks 0..3
    const int tid = threadIdx.x, w = tid>>5, lane = tid&31, wm = w&1, wn = w>>1;
    extern __shared__ __align__(16) char sm[];
    uint32_t smA32 = smem_u32(sm), smW32 = smA32 + DEPTH*ASTG;
    constexpr int KCH = KP3/KS_DEC;             // 768
    constexpr int SK  = KCH/64;                 // 12
    const size_t kb0 = (size_t)ks*KCH*2;

    const char* wsrc[3]; uint32_t wdst[3];
#pragma unroll
    for (int i=0;i<3;i++){
        int id=tid+256*i, r=id>>3, c=id&7;
        wsrc[i] = (const char*)(g_WhhI[2] + (size_t)(nx*96+r)*KP3) + kb0 + c*16;
        wdst[i] = SWZ((uint32_t)(r*128+c*16));
    }
    size_t aoff[4]; uint32_t adst[4];
#pragma unroll
    for (int i=0;i<4;i++){
        int id=tid+256*i, r=id>>3, c=id&7;
        aoff[i] = (size_t)r*KP3*2 + kb0 + c*16;
        adst[i] = SWZ((uint32_t)(r*128+c*16));
    }
    const int arow_l = wm*64 + (lane&15);
    const int a_kb   = (lane>>4)*16;
    const int brow_l = wn*24 + (lane&7);
    const int b_kb   = ((lane>>3)&1)*16;
    const int gr = lane>>2, gc = (lane&3)*2;

    const int u = lane, xu = nx*32+u;
    const float br = g_bhhI[2][nx*96+u];
    const float bz = g_bhhI[2][nx*96+32+u];
    const float bn = g_bhhI[2][nx*96+64+u];
    float* pb = g_part[0][ks][nx];

    for (int t=0; t<TOUT; t++){
        const char* abase = (t==0) ? (const char*)g_d0A
                                   : (const char*)(g_fcA + (size_t)(t-1)*128*KP3);
        const char* asrc[4];
#pragma unroll
        for (int i=0;i<4;i++) asrc[i] = abase + aoff[i];
        float acc[4][3][4];
        mma_core<SK>(smA32, smW32, asrc, adst, wsrc, wdst, arow_l, a_kb, brow_l, b_kb, acc);
#pragma unroll
        for (int mi=0;mi<4;mi++)
#pragma unroll
            for (int h=0;h<2;h++){
                int m = wm*64+mi*16+gr+h*8;
#pragma unroll
                for (int ni=0;ni<3;ni++){
                    int n = wn*24+ni*8+gc;
                    float2 v = { acc[mi][ni][h*2], acc[mi][ni][h*2+1] };
                    *(float2*)&pb[m*96+n] = v;
                }
            }
        bar_sync(&g_barD, 128*(2*t+1));
        // distributed epilogue: m in [ks*32, ks*32+32), u = lane
        const float* hin  = t ? g_hFd[(t-1)&1] : g_d0F;
        float* hout = g_hFd[t&1];
        __nv_bfloat16* hA = g_fcA + (size_t)t*128*KP3;
        int ti = t ? t-1 : 0;
#pragma unroll
        for (int i=0;i<4;i++){
            int m = ks*32 + (tid>>5) + i*8;
            int tok = idx[m*TOUT + ti];
            const float* Urow = g_Ud + (size_t)tok*H3 + nx*96;
            float sr=0.f, sz=0.f, sn=0.f;
#pragma unroll
            for (int k2=0;k2<KS_DEC;k2++){
                const float* pp = g_part[0][k2][nx] + m*96;
                sr += pp[u]; sz += pp[32+u]; sn += pp[64+u];
            }
            float rr = 1.f/(1.f+expf(-(Urow[u]    + sr + br)));
            float zz = 1.f/(1.f+expf(-(Urow[32+u] + sz + bz)));
            float nn = tanhf(Urow[64+u] + rr*(sn + bn));
            float h  = (1.f-zz)*nn + zz*hin[(size_t)m*HID + xu];
            hout[(size_t)m*HID + xu] = h;
            __nv_bfloat16 hh = __float2bfloat16(h);
            hA[(size_t)m*KP3 + xu]         = hh;
            hA[(size_t)m*KP3 + HID + xu]   = hh;
            hA[(size_t)m*KP3 + 2*HID + xu] = __float2bfloat16(h - __bfloat162float(hh));
        }
        bar_sync(&g_barD, 128*(2*t+2));
    }
}

// ------------------------------- launch ------------------------------------
extern "C" void kernel_launch(void* const* d_in, const int* in_sizes, int n_in,
                              void* d_out, int out_size)
{
    const float* enc_emb   = (const float*)d_in[0];
    const float* enc_Wih_f = (const float*)d_in[1];
    const float* enc_Whh_f = (const float*)d_in[2];
    const float* enc_bih_f = (const float*)d_in[3];
    const float* enc_bhh_f = (const float*)d_in[4];
    const float* enc_Wih_b = (const float*)d_in[5];
    const float* enc_Whh_b = (const float*)d_in[6];
    const float* enc_bih_b = (const float*)d_in[7];
    const float* enc_bhh_b = (const float*)d_in[8];
    const float* dec_emb   = (const float*)d_in[9];
    const float* dec_Wih   = (const float*)d_in[10];
    const float* dec_Whh   = (const float*)d_in[11];
    const float* dec_bih   = (const float*)d_in[12];
    const float* dec_bhh   = (const float*)d_in[13];
    const float* fc_W      = (const float*)d_in[14];
    const float* fc_b      = (const float*)d_in[15];
    const int*   in_text   = (const int*)d_in[16];
    const int*   poses     = (const int*)d_in[18];
    float* out = (float*)d_out;

    cudaFuncSetAttribute(gk<0>,  cudaFuncAttributeMaxDynamicSharedMemorySize, SMTOT);
    cudaFuncSetAttribute(gk<1>,  cudaFuncAttributeMaxDynamicSharedMemorySize, SMTOT);
    cudaFuncSetAttribute(gk<4>,  cudaFuncAttributeMaxDynamicSharedMemorySize, SMTOT);
    cudaFuncSetAttribute(enc_run, cudaFuncAttributeMaxDynamicSharedMemorySize, SMTOT);
    cudaFuncSetAttribute(dec_run, cudaFuncAttributeMaxDynamicSharedMemorySize, SMTOT);

    prep_a<<<dim3(128,2),256>>>(enc_emb, dec_emb);
    prep_w<<<dim3(256,7),256>>>(enc_Wih_f, enc_bih_f, enc_Wih_b, enc_bih_b,
                                dec_Wih, dec_bih, enc_Whh_f, enc_bhh_f,
                                enc_Whh_b, enc_bhh_b, dec_Whh, dec_bhh, fc_W);
    init_h<<<(128*KP3+255)/256,256>>>();

    gk<0><<<dim3(32,31,2),256,SMTOT>>>(nullptr, nullptr);
    gk<1><<<dim3(32,5,1), 256,SMTOT>>>(nullptr, nullptr);

    enc_run<<<128,256,SMTOT>>>(in_text);
    combine<<<(128*HID+255)/256,256>>>();
    dec_run<<<128,256,SMTOT>>>(poses);

    gk<4><<<dim3(6,90,1),256,SMTOT>>>(fc_b, out);
}